// round 17
// baseline (speedup 1.0000x reference)
#include <cuda_runtime.h>
#include <cstdint>

#define BATCH 256

__device__ float g_bufA[BATCH * 64 * 32 * 32]; // 64 MB
__device__ float g_bufB[BATCH * 64 * 32 * 32];

// ---- packed f32x2 helpers --------------------------------------------------
typedef unsigned long long f2_t;

__device__ __forceinline__ f2_t pk2(float a, float b) {
    f2_t r;
    asm("mov.b64 %0, {%1, %2};" : "=l"(r)
        : "r"(__float_as_uint(a)), "r"(__float_as_uint(b)));
    return r;
}
__device__ __forceinline__ void upk2(f2_t v, float& a, float& b) {
    unsigned lo, hi;
    asm("mov.b64 {%0, %1}, %2;" : "=r"(lo), "=r"(hi) : "l"(v));
    a = __uint_as_float(lo);
    b = __uint_as_float(hi);
}
__device__ __forceinline__ f2_t fma2(f2_t a, f2_t b, f2_t c) {
    f2_t d;
    asm("fma.rn.f32x2 %0, %1, %2, %3;" : "=l"(d) : "l"(a), "l"(b), "l"(c));
    return d;
}

// ---------------------------------------------------------------------------
// Layer 0 (fma2 version): weights pre-paired (oc,oc+1) in smem; input splats
// hoisted; 32 oc-pair iterations of 8 LDS.64 + 32 fma2.
// ---------------------------------------------------------------------------
__global__ __launch_bounds__(256)
void k_layer0(const float* __restrict__ x, const float* __restrict__ W0,
              const float* __restrict__ b0, float* __restrict__ out)
{
    __shared__ f2_t wsp[256];  // [ocpair][k(8)] : (w[2p][k], w[2p+1][k])
    __shared__ f2_t bsp[32];   // (b[2p], b[2p+1])
    const int tid = threadIdx.x;
    {
        int p = tid >> 3, k = tid & 7;   // 256 threads = 32 pairs x 8 k
        wsp[tid] = pk2(W0[(2 * p) * 16 + k], W0[(2 * p + 1) * 16 + k]);
        if (tid < 32) bsp[tid] = pk2(b0[2 * tid], b0[2 * tid + 1]);
    }
    __syncthreads();

    const int pos = blockIdx.x * 256 + tid;
    const int b = blockIdx.y;
    const int i = pos >> 5, j = pos & 31;
    const int pr1 = (2 * i + 1 == 63) ? 0 : 2 * i + 1;
    const int pc1 = (2 * j + 1 == 63) ? 0 : 2 * j + 1;
    int R[4]  = {2 * i, 2 * i + 1, pr1, pr1 + 1};
    int Cc[4] = {2 * j, 2 * j + 1, pc1, pc1 + 1};

    const float* xb = x + (size_t)b * 4096;
    f2_t sp_p[16], sp_n[16];
#pragma unroll
    for (int a = 0; a < 4; a++)
#pragma unroll
        for (int c = 0; c < 4; c++) {
            float v = xb[R[a] * 64 + Cc[c]];
            float p = fmaxf(v, 0.f), nn = fmaxf(-v, 0.f);
            sp_p[a * 4 + c] = pk2(p, p);
            sp_n[a * 4 + c] = pk2(nn, nn);
        }

    float* ob = out + (size_t)b * 64 * 1024 + i * 32 + j;
#pragma unroll 4
    for (int p = 0; p < 32; p++) {
        f2_t w[8];
#pragma unroll
        for (int k = 0; k < 8; k++) w[k] = wsp[p * 8 + k];
        f2_t bias = bsp[p];
        f2_t acc[4];
        acc[0] = bias; acc[1] = bias; acc[2] = bias; acc[3] = bias;
#pragma unroll
        for (int P = 0; P < 2; P++)
#pragma unroll
            for (int Q = 0; Q < 2; Q++) {
                const int t = P * 2 + Q;
#pragma unroll
                for (int kh = 0; kh < 2; kh++)
#pragma unroll
                    for (int kw = 0; kw < 2; kw++) {
                        int idx = (2 * P + kh) * 4 + (2 * Q + kw);
                        acc[t] = fma2(sp_p[idx], w[kh * 2 + kw], acc[t]);
                        acc[t] = fma2(sp_n[idx], w[4 + kh * 2 + kw], acc[t]);
                    }
            }
        float e0, o0, e1, o1, e2, o2, e3, o3;
        upk2(acc[0], e0, o0);
        upk2(acc[1], e1, o1);
        upk2(acc[2], e2, o2);
        upk2(acc[3], e3, o3);
        float se = fmaxf(e0, 0.f) + fmaxf(e1, 0.f) + fmaxf(e2, 0.f) + fmaxf(e3, 0.f);
        float so = fmaxf(o0, 0.f) + fmaxf(o1, 0.f) + fmaxf(o2, 0.f) + fmaxf(o3, 0.f);
        ob[(2 * p) * 1024]     = 0.25f * se;
        ob[(2 * p + 1) * 1024] = 0.25f * so;
    }
}

// ---------------------------------------------------------------------------
// Recursion level (R14-proven): 16 oc/thread, parity-plane smem, conv-grid
// wrap via rt/ct select tables, child-uniform warps, MINB=2, large BB.
// Used for L1..L3.
// ---------------------------------------------------------------------------
template <int S, int BB, int G>
__global__ __launch_bounds__(256, 2)
void k_layer(const float* __restrict__ in, const float* __restrict__ W,
             const float* __restrict__ bias, float* __restrict__ out)
{
    constexpr int H = S / 2;
    constexpr int HH = H * H;
    constexpr int Nin = G * G;
    constexpr int Nout = 4 * Nin;
    constexpr int CB = S * S;
    constexpr int PAD = (HH < 32) ? HH : 0;
    constexpr int CHB = 16 * CB + PAD;
    constexpr int WCS = 1024;
    constexpr int perB = 16 * S * S;
    constexpr int ITERS = (BB * HH) / 64;

    extern __shared__ float sm[];
    float* ws  = sm;              // 4*WCS : ws[child][tap(ci*4+kh*2+kw)][16oc]
    float* bs  = sm + 4 * WCS;
    float* ins = bs + 64;

    const int tid = threadIdx.x;
    const int n = blockIdx.x;
    const int b0 = blockIdx.y * BB;

    const float* Wg = W + (size_t)n * 4096;
    for (int t = tid; t < 4096; t += 256) {
        int ol = t >> 6, tap = t & 63;
        ws[(ol >> 4) * WCS + tap * 16 + (ol & 15)] = Wg[t];
    }
    if (tid < 64) bs[tid] = bias[n * 64 + tid];

    for (int t = tid; t < BB * perB; t += 256) {
        int bl = t / perB, rem = t - bl * perB;
        int ci = rem / CB, sp = rem - ci * CB;
        int r = sp / S, c = sp - r * S;
        ins[bl * CHB + ci * CB + ((r & 1) * 2 + (c & 1)) * HH
            + (r >> 1) * H + (c >> 1)]
            = in[((size_t)(b0 + bl) * Nin + n) * perB + rem];
    }
    __syncthreads();

    const int Ay = n / G, Ax = n % G;
    const int lane = tid & 31, warp = tid >> 5;
    const int child = warp & 3;
    const int wk0 = lane + ((warp >> 2) << 5);   // 0..63

    const float* wc = ws + child * WCS;
    const int yl = child >> 1, xl = child & 1;
    const int nprime = (2 * Ay + yl) * (2 * G) + (2 * Ax + xl);

#pragma unroll
    for (int it = 0; it < ITERS; it++) {
        const int v = wk0 + (it << 6);
        const int j = v % H;
        const int i = (v / H) % H;
        const int bl = v / HH;

        const bool wi = (i == H - 1);
        const bool wj = (j == H - 1);
        const int rt1 = 2 * HH + i * H;
        const int rt[4] = {i * H, rt1, wi ? 0 : rt1, wi ? 2 * HH : (i + 1) * H};
        const int ct1 = HH + j;
        const int ct[4] = {j, ct1, wj ? 0 : ct1, wj ? HH : (j + 1)};

        const float* ib = ins + bl * CHB;

        f2_t acc[8][4];
#pragma unroll
        for (int k = 0; k < 8; k++) {
            f2_t bv = pk2(bs[child * 16 + 2 * k], bs[child * 16 + 2 * k + 1]);
            acc[k][0] = bv; acc[k][1] = bv; acc[k][2] = bv; acc[k][3] = bv;
        }

#pragma unroll 4
        for (int ci = 0; ci < 16; ci++) {
            const float* cb = ib + ci * CB;
            float xv[4][4];
#pragma unroll
            for (int a = 0; a < 4; a++)
#pragma unroll
                for (int b = 0; b < 4; b++)
                    xv[a][b] = cb[rt[a] + ct[b]];

#pragma unroll
            for (int kh = 0; kh < 2; kh++)
#pragma unroll
                for (int kw = 0; kw < 2; kw++) {
                    const ulonglong2* wt2 =
                        (const ulonglong2*)(wc + (ci * 4 + kh * 2 + kw) * 16);
                    f2_t vs0 = pk2(xv[kh][kw],         xv[kh][kw]);
                    f2_t vs1 = pk2(xv[kh][2 + kw],     xv[kh][2 + kw]);
                    f2_t vs2 = pk2(xv[2 + kh][kw],     xv[2 + kh][kw]);
                    f2_t vs3 = pk2(xv[2 + kh][2 + kw], xv[2 + kh][2 + kw]);
#pragma unroll
                    for (int m = 0; m < 4; m++) {
                        ulonglong2 ww = wt2[m];
                        acc[2 * m][0]     = fma2(ww.x, vs0, acc[2 * m][0]);
                        acc[2 * m][1]     = fma2(ww.x, vs1, acc[2 * m][1]);
                        acc[2 * m][2]     = fma2(ww.x, vs2, acc[2 * m][2]);
                        acc[2 * m][3]     = fma2(ww.x, vs3, acc[2 * m][3]);
                        acc[2 * m + 1][0] = fma2(ww.y, vs0, acc[2 * m + 1][0]);
                        acc[2 * m + 1][1] = fma2(ww.y, vs1, acc[2 * m + 1][1]);
                        acc[2 * m + 1][2] = fma2(ww.y, vs2, acc[2 * m + 1][2]);
                        acc[2 * m + 1][3] = fma2(ww.y, vs3, acc[2 * m + 1][3]);
                    }
                }
        }

        float* ob = out + ((size_t)(b0 + bl) * Nout + nprime) * 16 * HH
                        + i * H + j;
#pragma unroll
        for (int k = 0; k < 8; k++) {
            float a0, c0, a1, c1, a2, c2, a3, c3;
            upk2(acc[k][0], a0, c0);
            upk2(acc[k][1], a1, c1);
            upk2(acc[k][2], a2, c2);
            upk2(acc[k][3], a3, c3);
            float e = fmaxf(a0, 0.f) + fmaxf(a1, 0.f) + fmaxf(a2, 0.f) + fmaxf(a3, 0.f);
            float o = fmaxf(c0, 0.f) + fmaxf(c1, 0.f) + fmaxf(c2, 0.f) + fmaxf(c3, 0.f);
            ob[(2 * k) * HH]     = 0.25f * e;
            ob[(2 * k + 1) * HH] = 0.25f * o;
        }
    }
}

// ---------------------------------------------------------------------------
// Layer 4 special (R16-proven): 9 conv cells computed once, pool in epilogue.
// ---------------------------------------------------------------------------
__global__ __launch_bounds__(256, 2)
void k_layer4(const float* __restrict__ in, const float* __restrict__ W,
              const float* __restrict__ bias, float* __restrict__ out)
{
    constexpr int G = 16, Nin = 256, Nout = 1024, BB = 64;
    constexpr int CHB = 257;
    constexpr int WCS = 1024;

    extern __shared__ float sm[];
    float* ws  = sm;
    float* bs  = sm + 4 * WCS;
    float* ins = bs + 64;

    const int tid = threadIdx.x;
    const int n = blockIdx.x;
    const int b0 = blockIdx.y * BB;

    const float* Wg = W + (size_t)n * 4096;
    for (int t = tid; t < 4096; t += 256) {
        int ol = t >> 6, tap = t & 63;
        ws[(ol >> 4) * WCS + tap * 16 + (ol & 15)] = Wg[t];
    }
    if (tid < 64) bs[tid] = bias[n * 64 + tid];

    for (int t = tid; t < BB * 256; t += 256) {
        int bl = t >> 8, rem = t & 255;
        ins[bl * CHB + rem] = in[((size_t)(b0 + bl) * Nin + n) * 256 + rem];
    }
    __syncthreads();

    const int Ay = n / G, Ax = n % G;
    const int lane = tid & 31, warp = tid >> 5;
    const int child = warp & 3;
    const int half = warp >> 2;
    const float* wc = ws + child * WCS + half * 8;
    const int yl = child >> 1, xl = child & 1;
    const int nprime = (2 * Ay + yl) * (2 * G) + (2 * Ax + xl);

#pragma unroll
    for (int it = 0; it < 2; it++) {
        const int bl = lane + (it << 5);
        const float* ib = ins + bl * CHB;

        f2_t acc[9][4];
#pragma unroll
        for (int m = 0; m < 4; m++) {
            f2_t bv = pk2(bs[child * 16 + half * 8 + 2 * m],
                          bs[child * 16 + half * 8 + 2 * m + 1]);
#pragma unroll
            for (int cell = 0; cell < 9; cell++) acc[cell][m] = bv;
        }

#pragma unroll 2
        for (int ci = 0; ci < 16; ci++) {
            f2_t w[4][4];
#pragma unroll
            for (int tap = 0; tap < 4; tap++) {
                const ulonglong2* wt2 =
                    (const ulonglong2*)(wc + (ci * 4 + tap) * 16);
                ulonglong2 u0 = wt2[0];
                ulonglong2 u1 = wt2[1];
                w[tap][0] = u0.x; w[tap][1] = u0.y;
                w[tap][2] = u1.x; w[tap][3] = u1.y;
            }
#pragma unroll
            for (int a = 0; a < 4; a++)
#pragma unroll
                for (int b = 0; b < 4; b++) {
                    float xx = ib[ci * 16 + a * 4 + b];
                    f2_t vs = pk2(xx, xx);
#pragma unroll
                    for (int kh = 0; kh < 2; kh++) {
                        if (a - kh < 0 || a - kh > 2) continue;
#pragma unroll
                        for (int kw = 0; kw < 2; kw++) {
                            if (b - kw < 0 || b - kw > 2) continue;
                            const int tap = kh * 2 + kw;
                            const int cell = (a - kh) * 3 + (b - kw);
#pragma unroll
                            for (int m = 0; m < 4; m++)
                                acc[cell][m] = fma2(w[tap][m], vs, acc[cell][m]);
                        }
                    }
                }
        }

        float* ob = out + ((size_t)(b0 + bl) * Nout + nprime) * 64
                        + half * 32;
#pragma unroll
        for (int m = 0; m < 4; m++) {
            float ce[9], co[9];
#pragma unroll
            for (int cell = 0; cell < 9; cell++) {
                float a0, a1;
                upk2(acc[cell][m], a0, a1);
                ce[cell] = fmaxf(a0, 0.f);
                co[cell] = fmaxf(a1, 0.f);
            }
            float4 oe, oo;
            oe.x = ce[0] + ce[1] + ce[3] + ce[4];
            oe.y = ce[2] + ce[0] + ce[5] + ce[3];
            oe.z = ce[6] + ce[7] + ce[0] + ce[1];
            oe.w = ce[8] + ce[6] + ce[2] + ce[0];
            oo.x = co[0] + co[1] + co[3] + co[4];
            oo.y = co[2] + co[0] + co[5] + co[3];
            oo.z = co[6] + co[7] + co[0] + co[1];
            oo.w = co[8] + co[6] + co[2] + co[0];
            oe.x *= 0.25f; oe.y *= 0.25f; oe.z *= 0.25f; oe.w *= 0.25f;
            oo.x *= 0.25f; oo.y *= 0.25f; oo.z *= 0.25f; oo.w *= 0.25f;
            *(float4*)(ob + (2 * m) * 4)     = oe;
            *(float4*)(ob + (2 * m + 1) * 4) = oo;
        }
    }
}

// ---------------------------------------------------------------------------
// Layer 5 special (R15-proven): out = relu(bias + conv), 4 batch slots/thread.
// ---------------------------------------------------------------------------
__global__ __launch_bounds__(256, 2)
void k_layer5(const float* __restrict__ in, const float* __restrict__ W,
              const float* __restrict__ bias, float* __restrict__ out)
{
    constexpr int G = 32, Nin = 1024, Nout = 4096, BB = 256;
    constexpr int CHB = 65;
    constexpr int WCS = 1024;

    extern __shared__ float sm[];
    float* ws  = sm;
    float* bs  = sm + 4 * WCS;
    float* ins = bs + 64;

    const int tid = threadIdx.x;
    const int n = blockIdx.x;

    const float* Wg = W + (size_t)n * 4096;
    for (int t = tid; t < 4096; t += 256) {
        int ol = t >> 6, tap = t & 63;
        ws[(ol >> 4) * WCS + tap * 16 + (ol & 15)] = Wg[t];
    }
    if (tid < 64) bs[tid] = bias[n * 64 + tid];

    for (int t = tid; t < BB * 64; t += 256) {
        int bl = t >> 6, rem = t & 63;
        ins[bl * CHB + rem] = in[((size_t)bl * Nin + n) * 64 + rem];
    }
    __syncthreads();

    const int Ay = n / G, Ax = n % G;
    const int lane = tid & 31, warp = tid >> 5;
    const int child = warp & 3;
    const int wk0 = lane + ((warp >> 2) << 5);

    const float* wc = ws + child * WCS;
    const int yl = child >> 1, xl = child & 1;
    const int nprime = (2 * Ay + yl) * (2 * G) + (2 * Ax + xl);

    const float* ib = ins + wk0 * CHB;

    f2_t acc[8][4];
#pragma unroll
    for (int k = 0; k < 8; k++) {
        f2_t bv = pk2(bs[child * 16 + 2 * k], bs[child * 16 + 2 * k + 1]);
        acc[k][0] = bv; acc[k][1] = bv; acc[k][2] = bv; acc[k][3] = bv;
    }

#pragma unroll 4
    for (int ci = 0; ci < 16; ci++) {
#pragma unroll
        for (int t = 0; t < 4; t++) {
            float x0 = ib[ci * 4 + t];
            float x1 = ib[64 * CHB + ci * 4 + t];
            float x2 = ib[128 * CHB + ci * 4 + t];
            float x3 = ib[192 * CHB + ci * 4 + t];
            const ulonglong2* wt2 = (const ulonglong2*)(wc + (ci * 4 + t) * 16);
            f2_t vs0 = pk2(x0, x0), vs1 = pk2(x1, x1);
            f2_t vs2 = pk2(x2, x2), vs3 = pk2(x3, x3);
#pragma unroll
            for (int m = 0; m < 4; m++) {
                ulonglong2 ww = wt2[m];
                acc[2 * m][0]     = fma2(ww.x, vs0, acc[2 * m][0]);
                acc[2 * m][1]     = fma2(ww.x, vs1, acc[2 * m][1]);
                acc[2 * m][2]     = fma2(ww.x, vs2, acc[2 * m][2]);
                acc[2 * m][3]     = fma2(ww.x, vs3, acc[2 * m][3]);
                acc[2 * m + 1][0] = fma2(ww.y, vs0, acc[2 * m + 1][0]);
                acc[2 * m + 1][1] = fma2(ww.y, vs1, acc[2 * m + 1][1]);
                acc[2 * m + 1][2] = fma2(ww.y, vs2, acc[2 * m + 1][2]);
                acc[2 * m + 1][3] = fma2(ww.y, vs3, acc[2 * m + 1][3]);
            }
        }
    }

#pragma unroll
    for (int s = 0; s < 4; s++) {
        const int bl = wk0 + 64 * s;
        float* ob = out + ((size_t)bl * Nout + nprime) * 16;
#pragma unroll
        for (int q = 0; q < 4; q++) {
            float a0, a1, a2, a3;
            upk2(acc[2 * q][s], a0, a1);
            upk2(acc[2 * q + 1][s], a2, a3);
            float4 o;
            o.x = fmaxf(a0, 0.f); o.y = fmaxf(a1, 0.f);
            o.z = fmaxf(a2, 0.f); o.w = fmaxf(a3, 0.f);
            *(float4*)(ob + 4 * q) = o;
        }
    }
}

// ---------------------------------------------------------------------------
// FT layer (fma2): Wft pre-paired into smem, hoisted into registers across
// the 16-batch loop. Per batch: 4 LDG.128 + 16 pk2 + 32 fma2.
// ---------------------------------------------------------------------------
__global__ __launch_bounds__(256)
void k_ft(const float* __restrict__ v, const float* __restrict__ Wft,
          const float* __restrict__ bft, float* __restrict__ out)
{
    extern __shared__ f2_t smf[];
    f2_t* wsm = smf;           // [n_local(256)][c(16)][ocpair(2)]
    f2_t* bsm = smf + 8192;    // [n_local][2]

    const int tid = threadIdx.x;
    const int nb = blockIdx.x;
    const int yb = blockIdx.y;

    // build pairs: wsm[nl*32 + c*2 + op] = (W[n][2op][c], W[n][2op+1][c])
    for (int t = tid; t < 8192; t += 256) {
        int nl = t >> 5, c2 = t & 31;
        int c = c2 >> 1, op = c2 & 1;
        const float* wp = Wft + (size_t)nb * 16384 + nl * 64 + (2 * op) * 16 + c;
        wsm[t] = pk2(wp[0], wp[16]);
    }
    for (int t = tid; t < 512; t += 256) {
        int nl = t >> 1, op = t & 1;
        const float* bp = bft + nb * 1024 + nl * 4 + 2 * op;
        bsm[t] = pk2(bp[0], bp[1]);
    }
    __syncthreads();

    const int n = nb * 256 + tid;
    // hoist this thread's weights to registers (reused for all 16 batches)
    f2_t wr[16][2];
#pragma unroll
    for (int c = 0; c < 16; c++) {
        wr[c][0] = wsm[tid * 32 + c * 2 + 0];
        wr[c][1] = wsm[tid * 32 + c * 2 + 1];
    }
    const f2_t bias0 = bsm[tid * 2 + 0];
    const f2_t bias1 = bsm[tid * 2 + 1];

#pragma unroll 1
    for (int bb = 0; bb < 16; bb++) {
        const int b = yb * 16 + bb;
        const float* vp = v + ((size_t)b * 4096 + n) * 16;
        f2_t a0 = bias0, a1 = bias1;
#pragma unroll
        for (int c = 0; c < 16; c += 4) {
            float4 t4 = *(const float4*)(vp + c);
            f2_t s0 = pk2(t4.x, t4.x);
            f2_t s1 = pk2(t4.y, t4.y);
            f2_t s2 = pk2(t4.z, t4.z);
            f2_t s3 = pk2(t4.w, t4.w);
            a0 = fma2(wr[c][0],     s0, a0);
            a1 = fma2(wr[c][1],     s0, a1);
            a0 = fma2(wr[c + 1][0], s1, a0);
            a1 = fma2(wr[c + 1][1], s1, a1);
            a0 = fma2(wr[c + 2][0], s2, a0);
            a1 = fma2(wr[c + 2][1], s2, a1);
            a0 = fma2(wr[c + 3][0], s3, a0);
            a1 = fma2(wr[c + 3][1], s3, a1);
        }
        float f0, f1, f2v, f3;
        upk2(a0, f0, f1);
        upk2(a1, f2v, f3);
        out[(size_t)b * 8192 + n]        = f0 - f1;
        out[(size_t)b * 8192 + 4096 + n] = f2v - f3;
    }
}

// ---------------------------------------------------------------------------

template <int S, int BB>
static inline int smem_b() {
    int HH = (S / 2) * (S / 2);
    int pad = (HH < 32) ? HH : 0;
    return (4 * 1024 + 64 + BB * (16 * S * S + pad)) * 4;
}

extern "C" void kernel_launch(void* const* d_in, const int* in_sizes, int n_in,
                              void* d_out, int out_size)
{
    (void)n_in; (void)out_size;
    const float* x  = (const float*)d_in[0];
    const float* W0 = (const float*)d_in[1];
    const float* b0 = (const float*)d_in[2];
    const float *W1, *b1, *W2, *b2, *W3, *b3, *W4, *b4, *W5, *b5, *Wft, *bft;
    if (in_sizes[3] == 262144) {
        Wft = (const float*)d_in[3];  bft = (const float*)d_in[4];
        W1 = (const float*)d_in[5];   b1 = (const float*)d_in[6];
        W2 = (const float*)d_in[7];   b2 = (const float*)d_in[8];
        W3 = (const float*)d_in[9];   b3 = (const float*)d_in[10];
        W4 = (const float*)d_in[11];  b4 = (const float*)d_in[12];
        W5 = (const float*)d_in[13];  b5 = (const float*)d_in[14];
    } else {
        W1 = (const float*)d_in[3];   b1 = (const float*)d_in[4];
        W2 = (const float*)d_in[5];   b2 = (const float*)d_in[6];
        W3 = (const float*)d_in[7];   b3 = (const float*)d_in[8];
        W4 = (const float*)d_in[9];   b4 = (const float*)d_in[10];
        W5 = (const float*)d_in[11];  b5 = (const float*)d_in[12];
        Wft = (const float*)d_in[13]; bft = (const float*)d_in[14];
    }
    float* out = (float*)d_out;

    float *bufA, *bufB;
    cudaGetSymbolAddress((void**)&bufA, g_bufA);
    cudaGetSymbolAddress((void**)&bufB, g_bufB);

    const int s1 = smem_b<32, 1>();                  // ~82 KB
    const int s2 = smem_b<16, 4>();                  // ~82 KB
    const int s3 = smem_b<8, 16>();                  // ~83 KB
    const int s4 = (4 * 1024 + 64 + 64 * 257) * 4;   // ~82 KB
    const int s5 = (4 * 1024 + 64 + 256 * 65) * 4;   // ~83 KB
    const int sft = (8192 + 512) * 8;                // ~68 KB (f2 units)
    cudaFuncSetAttribute(k_layer<32, 1, 2>,    cudaFuncAttributeMaxDynamicSharedMemorySize, s1);
    cudaFuncSetAttribute(k_layer<16, 4, 4>,    cudaFuncAttributeMaxDynamicSharedMemorySize, s2);
    cudaFuncSetAttribute(k_layer<8, 16, 8>,    cudaFuncAttributeMaxDynamicSharedMemorySize, s3);
    cudaFuncSetAttribute(k_layer4,             cudaFuncAttributeMaxDynamicSharedMemorySize, s4);
    cudaFuncSetAttribute(k_layer5,             cudaFuncAttributeMaxDynamicSharedMemorySize, s5);
    cudaFuncSetAttribute(k_ft,                 cudaFuncAttributeMaxDynamicSharedMemorySize, sft);

    k_layer0<<<dim3(4, BATCH), 256>>>(x, W0, b0, bufA);
    k_layer<32, 1, 2><<<dim3(4, 256), 256, s1>>>(bufA, W1, b1, bufB);
    k_layer<16, 4, 4><<<dim3(16, 64), 256, s2>>>(bufB, W2, b2, bufA);
    k_layer<8, 16, 8><<<dim3(64, 16), 256, s3>>>(bufA, W3, b3, bufB);
    k_layer4<<<dim3(256, 4), 256, s4>>>(bufB, W4, b4, bufA);
    k_layer5<<<dim3(1024, 1), 256, s5>>>(bufA, W5, b5, bufB);
    k_ft<<<dim3(16, 16), 256, sft>>>(bufB, Wft, bft, out);
}